// round 5
// baseline (speedup 1.0000x reference)
#include <cuda_runtime.h>
#include <cuda_bf16.h>
#include <math.h>
#include <stdint.h>

#define HID   512
#define PH    32
#define BSZ   2048
#define FOURH 2048
#define SLAB  (BSZ * HID)

#define TM 128
#define TN 256
#define KC 32
#define NCH (HID / KC)   // 16 k-chunks
#define NTHR 512

// stage layout (bytes): A tiles 128x32 bf16 = 8KB each, B tiles 256x32 bf16 = 16KB each
#define AH_OFF 0
#define AL_OFF 8192
#define BH_OFF 16384
#define BL_OFF 32768
#define STAGE  49152
#define NSTG   3
#define SMEM_DYN (NSTG * STAGE)

// ---------------- static device scratch ----------------
__device__ __nv_bfloat16 g_xh[(PH + 1) * (size_t)SLAB];
__device__ __nv_bfloat16 g_xl[(PH + 1) * (size_t)SLAB];
__device__ __nv_bfloat16 g_wh [FOURH * HID];
__device__ __nv_bfloat16 g_wl [FOURH * HID];
__device__ __nv_bfloat16 g_wh0[FOURH * HID];
__device__ __nv_bfloat16 g_wl0[FOURH * HID];
__device__ float g_bp[FOURH];
__device__ float g_c[(size_t)BSZ * HID];

// ---------------- helpers ----------------
__device__ __forceinline__ uint32_t smem_u32(const void* p) {
    uint32_t a;
    asm("{ .reg .u64 t; cvta.to.shared.u64 t, %1; cvt.u32.u64 %0, t; }" : "=r"(a) : "l"(p));
    return a;
}
__device__ __forceinline__ uint32_t smoff(int row, int q) {
    return (uint32_t)((row << 6) + (((q) ^ ((row >> 1) & 3)) << 4));
}
__device__ __forceinline__ void cp16(uint32_t dst, const void* src) {
    asm volatile("cp.async.cg.shared.global [%0], [%1], 16;" :: "r"(dst), "l"(src));
}
__device__ __forceinline__ void cp_commit() { asm volatile("cp.async.commit_group;"); }
template <int N>
__device__ __forceinline__ void cp_wait() {
    asm volatile("cp.async.wait_group %0;" :: "n"(N) : "memory");
}
__device__ __forceinline__ void ldsm4(uint32_t* r, uint32_t addr) {
    asm volatile("ldmatrix.sync.aligned.m8n8.x4.shared.b16 {%0,%1,%2,%3}, [%4];"
        : "=r"(r[0]), "=r"(r[1]), "=r"(r[2]), "=r"(r[3]) : "r"(addr));
}
__device__ __forceinline__ void mma16816(float* c, const uint32_t* a, const uint32_t* b) {
    asm volatile(
        "mma.sync.aligned.m16n8k16.row.col.f32.bf16.bf16.f32 "
        "{%0,%1,%2,%3}, {%4,%5,%6,%7}, {%8,%9}, {%0,%1,%2,%3};"
        : "+f"(c[0]), "+f"(c[1]), "+f"(c[2]), "+f"(c[3])
        : "r"(a[0]), "r"(a[1]), "r"(a[2]), "r"(a[3]), "r"(b[0]), "r"(b[1]));
}

// ---------------- prep ----------------
// W row r=q*512+hu -> rp = (hu/64)*256 + q*64 + (hu%64)
__global__ void prep_w(const float* __restrict__ Wih, const float* __restrict__ Whh,
                       const float* __restrict__ bih, const float* __restrict__ bhh) {
    int idx = blockIdx.x * blockDim.x + threadIdx.x;
    if (idx >= FOURH * HID) return;
    int r = idx / HID, k = idx - r * HID;
    int q = r >> 9, hu = r & 511;
    int rp = ((hu >> 6) << 8) + (q << 6) + (hu & 63);
    size_t o = (size_t)rp * HID + k;
    float w0 = Wih[idx];
    float ws = w0 + Whh[idx];
    __nv_bfloat16 h0 = __float2bfloat16(w0);
    g_wh0[o] = h0; g_wl0[o] = __float2bfloat16(w0 - __bfloat162float(h0));
    __nv_bfloat16 hs = __float2bfloat16(ws);
    g_wh[o] = hs;  g_wl[o] = __float2bfloat16(ws - __bfloat162float(hs));
    if (k == 0) g_bp[rp] = bih[r] + bhh[r];
}
__global__ void prep_z(const float* __restrict__ z) {
    int i = blockIdx.x * blockDim.x + threadIdx.x;
    if (i >= BSZ * HID) return;
    float v = z[i];
    __nv_bfloat16 h = __float2bfloat16(v);
    g_xh[i] = h;
    g_xl[i] = __float2bfloat16(v - __bfloat162float(h));
}

// ---------------- chunk loader (512 threads) ----------------
__device__ __forceinline__ void issue_chunk(char* stage,
                                            const __nv_bfloat16* Ah, const __nv_bfloat16* Al,
                                            const __nv_bfloat16* Bh, const __nv_bfloat16* Bl,
                                            int k0, int tid) {
    uint32_t sb = smem_u32(stage);
    // A tiles: 128 rows x 4 quads x {h,l} = 1024 x 16B; 2 per thread
#pragma unroll
    for (int i = 0; i < 2; ++i) {
        int idx = tid + (i << 9);
        const __nv_bfloat16* src = (idx & 512) ? Al : Ah;
        uint32_t toff = (idx & 512) ? AL_OFF : AH_OFF;
        int w = idx & 511, row = w >> 2, q = w & 3;
        cp16(sb + toff + smoff(row, q), src + (size_t)row * HID + k0 + q * 8);
    }
    // B tiles: 256 rows x 4 quads x {h,l} = 2048 x 16B; 4 per thread
#pragma unroll
    for (int i = 0; i < 4; ++i) {
        int idx = tid + (i << 9);
        const __nv_bfloat16* src = (idx & 1024) ? Bl : Bh;
        uint32_t toff = (idx & 1024) ? BL_OFF : BH_OFF;
        int w = idx & 1023, row = w >> 2, q = w & 3;
        cp16(sb + toff + smoff(row, q), src + (size_t)row * HID + k0 + q * 8);
    }
}

// ---------------- per-step: gates GEMM (3-product bf16 split) + LSTM epilogue ----------------
// 16 warps: wm = warp>>3 (M 2x64), wn = warp&7. Warp wn owns n8-blocks {wn, wn+8, wn+16, wn+24}
// = gates i,f,g,o for hidden units [8wn, 8wn+8): epilogue fully register-local.
__global__ __launch_bounds__(NTHR, 1)
void step_kernel(const __nv_bfloat16* __restrict__ xh, const __nv_bfloat16* __restrict__ xl,
                 const __nv_bfloat16* __restrict__ wh, const __nv_bfloat16* __restrict__ wl,
                 __nv_bfloat16* __restrict__ xh_o, __nv_bfloat16* __restrict__ xl_o,
                 int t0) {
    extern __shared__ char dyn[];
    __shared__ float bias_sm[TN];
    const int tid = threadIdx.x;
    const int lane = tid & 31, warp = tid >> 5;
    const int wm = warp >> 3, wn = warp & 7;
    const int mb = blockIdx.x, nb = blockIdx.y;

    if (tid < TN) bias_sm[tid] = g_bp[nb * TN + tid];

    const __nv_bfloat16* Ah = xh + (size_t)(mb * TM) * HID;
    const __nv_bfloat16* Al = xl + (size_t)(mb * TM) * HID;
    const __nv_bfloat16* Bh = wh + (size_t)(nb * TN) * HID;
    const __nv_bfloat16* Bl = wl + (size_t)(nb * TN) * HID;

    float acc[4][4][4];   // [mi][gate][frag]
#pragma unroll
    for (int mi = 0; mi < 4; ++mi)
#pragma unroll
        for (int g = 0; g < 4; ++g)
#pragma unroll
            for (int r = 0; r < 4; ++r) acc[mi][g][r] = 0.f;

    issue_chunk(dyn, Ah, Al, Bh, Bl, 0, tid);
    cp_commit();
    issue_chunk(dyn + STAGE, Ah, Al, Bh, Bl, KC, tid);
    cp_commit();

    // per-lane fragment address components
    const int a_row = wm * 64 + (lane & 7) + ((lane >> 3) & 1) * 8;  // + mi*16
    const int a_q0  = (lane >> 4);                                   // + 2*s
    const int b_g   = lane >> 3;                                     // gate (matrix) index
    const int b_row = 8 * (wn + 8 * b_g) + (lane & 7);               // B row for ldsm

    int stg = 0;
    for (int c = 0; c < NCH; ++c) {
        if (c + 2 < NCH) {
            int ns = stg + 2; if (ns >= NSTG) ns -= NSTG;
            issue_chunk(dyn + ns * STAGE, Ah, Al, Bh, Bl, (c + 2) * KC, tid);
        }
        cp_commit();
        cp_wait<2>();
        __syncthreads();
        uint32_t st = smem_u32(dyn + stg * STAGE);
#pragma unroll
        for (int s = 0; s < 2; ++s) {
            uint32_t ah[4][4], al[4][4], bh[4][2], bl[4][2];
            // B-hi: 2 ldsm4, matrix g = gate g (lane octet g supplies its rows)
            {
                uint32_t r0[4], r1[4];
                ldsm4(r0, st + BH_OFF + smoff(b_row, 2 * s));
                ldsm4(r1, st + BH_OFF + smoff(b_row, 2 * s + 1));
#pragma unroll
                for (int g = 0; g < 4; ++g) { bh[g][0] = r0[g]; bh[g][1] = r1[g]; }
            }
#pragma unroll
            for (int mi = 0; mi < 4; ++mi)
                ldsm4(ah[mi], st + AH_OFF + smoff(a_row + mi * 16, a_q0 + 2 * s));
#pragma unroll
            for (int mi = 0; mi < 4; ++mi)
#pragma unroll
                for (int g = 0; g < 4; ++g) mma16816(acc[mi][g], ah[mi], bh[g]);
#pragma unroll
            for (int mi = 0; mi < 4; ++mi)
                ldsm4(al[mi], st + AL_OFF + smoff(a_row + mi * 16, a_q0 + 2 * s));
#pragma unroll
            for (int mi = 0; mi < 4; ++mi)
#pragma unroll
                for (int g = 0; g < 4; ++g) mma16816(acc[mi][g], al[mi], bh[g]);
            {
                uint32_t r0[4], r1[4];
                ldsm4(r0, st + BL_OFF + smoff(b_row, 2 * s));
                ldsm4(r1, st + BL_OFF + smoff(b_row, 2 * s + 1));
#pragma unroll
                for (int g = 0; g < 4; ++g) { bl[g][0] = r0[g]; bl[g][1] = r1[g]; }
            }
#pragma unroll
            for (int mi = 0; mi < 4; ++mi)
#pragma unroll
                for (int g = 0; g < 4; ++g) mma16816(acc[mi][g], ah[mi], bl[g]);
        }
        __syncthreads();
        ++stg; if (stg >= NSTG) stg = 0;
    }

    // ---- fused LSTM epilogue, fully in registers ----
    const int gq = lane >> 2, sq = lane & 3;
#pragma unroll
    for (int mi = 0; mi < 4; ++mi) {
#pragma unroll
        for (int r = 0; r < 4; ++r) {
            int rowl = wm * 64 + mi * 16 + gq + (r >> 1) * 8;
            int u = 8 * wn + 2 * sq + (r & 1);
            int row = mb * TM + rowl;
            int hu = nb * 64 + u;
            float gi = acc[mi][0][r] + bias_sm[u];
            float gf = acc[mi][1][r] + bias_sm[64 + u];
            float gg = acc[mi][2][r] + bias_sm[128 + u];
            float go = acc[mi][3][r] + bias_sm[192 + u];
            float cold = t0 ? 0.f : g_c[(size_t)row * HID + hu];
            float si = 1.f / (1.f + __expf(-gi));
            float sf = 1.f / (1.f + __expf(-gf));
            float so = 1.f / (1.f + __expf(-go));
            float tg = 2.f / (1.f + __expf(-2.f * gg)) - 1.f;
            float cn = fmaf(sf, cold, si * tg);
            float tc = 2.f / (1.f + __expf(-2.f * cn)) - 1.f;
            float hn = so * tc;
            g_c[(size_t)row * HID + hu] = cn;
            __nv_bfloat16 bhv = __float2bfloat16(hn);
            xh_o[(size_t)row * HID + hu] = bhv;
            xl_o[(size_t)row * HID + hu] = __float2bfloat16(hn - __bfloat162float(bhv));
        }
    }
}

// ---------------- final projection: all 32 steps in one kernel ----------------
__global__ void out_all(const float* __restrict__ Wd, const float* __restrict__ bd,
                        float* __restrict__ Y) {
    int wg = blockIdx.x * 8 + (threadIdx.x >> 5);
    int lane = threadIdx.x & 31;
    int t = wg & (PH - 1), row = wg >> 5;
    const __nv_bfloat16* xh = g_xh + (size_t)(t + 1) * SLAB + (size_t)row * HID;
    const __nv_bfloat16* xl = g_xl + (size_t)(t + 1) * SLAB + (size_t)row * HID;
    float s0 = 0.f, s1 = 0.f;
    for (int k = lane; k < HID; k += 32) {
        float hv = __bfloat162float(xh[k]) + __bfloat162float(xl[k]);
        s0 = fmaf(hv, Wd[k], s0);
        s1 = fmaf(hv, Wd[HID + k], s1);
    }
#pragma unroll
    for (int o = 16; o > 0; o >>= 1) {
        s0 += __shfl_xor_sync(0xffffffffu, s0, o);
        s1 += __shfl_xor_sync(0xffffffffu, s1, o);
    }
    if (lane == 0) {
        Y[(size_t)row * (PH * 2) + t * 2 + 0] = s0 + bd[0];
        Y[(size_t)row * (PH * 2) + t * 2 + 1] = s1 + bd[1];
    }
}

extern "C" void kernel_launch(void* const* d_in, const int* in_sizes, int n_in,
                              void* d_out, int out_size) {
    // metadata order: hist, z, W_ih, W_hh, b_ih, b_hh, W_d, b_d
    const float* z   = (const float*)d_in[1];
    const float* Wih = (const float*)d_in[2];
    const float* Whh = (const float*)d_in[3];
    const float* bih = (const float*)d_in[4];
    const float* bhh = (const float*)d_in[5];
    const float* Wd  = (const float*)d_in[6];
    const float* bd  = (const float*)d_in[7];
    float* Y = (float*)d_out;

    __nv_bfloat16 *xh, *xl, *wh, *wl, *wh0, *wl0;
    cudaGetSymbolAddress((void**)&xh,  g_xh);
    cudaGetSymbolAddress((void**)&xl,  g_xl);
    cudaGetSymbolAddress((void**)&wh,  g_wh);
    cudaGetSymbolAddress((void**)&wl,  g_wl);
    cudaGetSymbolAddress((void**)&wh0, g_wh0);
    cudaGetSymbolAddress((void**)&wl0, g_wl0);

    cudaFuncSetAttribute(step_kernel, cudaFuncAttributeMaxDynamicSharedMemorySize, SMEM_DYN);

    prep_w<<<(FOURH * HID + 255) / 256, 256>>>(Wih, Whh, bih, bhh);
    prep_z<<<(BSZ * HID + 255) / 256, 256>>>(z);

    dim3 grid(BSZ / TM, FOURH / TN);   // 16 x 8 = 128 CTAs
    for (int t = 0; t < PH; ++t) {
        const __nv_bfloat16* xhi = xh + (size_t)t * SLAB;
        const __nv_bfloat16* xli = xl + (size_t)t * SLAB;
        __nv_bfloat16* xho = xh + (size_t)(t + 1) * SLAB;
        __nv_bfloat16* xlo = xl + (size_t)(t + 1) * SLAB;
        step_kernel<<<grid, NTHR, SMEM_DYN>>>(xhi, xli,
                                              t == 0 ? wh0 : wh, t == 0 ? wl0 : wl,
                                              xho, xlo, t == 0 ? 1 : 0);
    }
    out_all<<<BSZ * PH / 8, 256>>>(Wd, bd, Y);
}

// round 6
// speedup vs baseline: 1.2218x; 1.2218x over previous
#include <cuda_runtime.h>
#include <cuda_bf16.h>
#include <math.h>
#include <stdint.h>

#define HID   512
#define PH    32
#define BSZ   2048
#define FOURH 2048
#define SLAB  (BSZ * HID)

#define TM 128
#define TN 256
#define KC 32
#define NCH (HID / KC)   // 16 k-chunks
#define NTHR 512

// stage layout (bytes): A tiles 128x32 bf16 = 8KB each, B tiles 256x32 bf16 = 16KB each
#define AH_OFF 0
#define AL_OFF 8192
#define BH_OFF 16384
#define BL_OFF 32768
#define STAGE  49152
#define NSTG   4
#define SMEM_DYN (NSTG * STAGE)

// ---------------- static device scratch ----------------
__device__ __nv_bfloat16 g_xh[(PH + 1) * (size_t)SLAB];
__device__ __nv_bfloat16 g_xl[(PH + 1) * (size_t)SLAB];
__device__ __nv_bfloat16 g_wh [FOURH * HID];
__device__ __nv_bfloat16 g_wl [FOURH * HID];
__device__ __nv_bfloat16 g_wh0[FOURH * HID];
__device__ __nv_bfloat16 g_wl0[FOURH * HID];
__device__ float g_bp[FOURH];
__device__ float g_c[(size_t)BSZ * HID];

// ---------------- helpers ----------------
__device__ __forceinline__ uint32_t smem_u32(const void* p) {
    uint32_t a;
    asm("{ .reg .u64 t; cvta.to.shared.u64 t, %1; cvt.u32.u64 %0, t; }" : "=r"(a) : "l"(p));
    return a;
}
__device__ __forceinline__ uint32_t smoff(int row, int q) {
    return (uint32_t)((row << 6) + (((q) ^ ((row >> 1) & 3)) << 4));
}
__device__ __forceinline__ void cp16(uint32_t dst, const void* src) {
    asm volatile("cp.async.cg.shared.global [%0], [%1], 16;" :: "r"(dst), "l"(src));
}
__device__ __forceinline__ void cp_commit() { asm volatile("cp.async.commit_group;"); }
template <int N>
__device__ __forceinline__ void cp_wait() {
    asm volatile("cp.async.wait_group %0;" :: "n"(N) : "memory");
}
__device__ __forceinline__ void ldsm4(uint32_t* r, uint32_t addr) {
    asm volatile("ldmatrix.sync.aligned.m8n8.x4.shared.b16 {%0,%1,%2,%3}, [%4];"
        : "=r"(r[0]), "=r"(r[1]), "=r"(r[2]), "=r"(r[3]) : "r"(addr));
}
__device__ __forceinline__ void mma16816(float* c, const uint32_t* a, const uint32_t* b) {
    asm volatile(
        "mma.sync.aligned.m16n8k16.row.col.f32.bf16.bf16.f32 "
        "{%0,%1,%2,%3}, {%4,%5,%6,%7}, {%8,%9}, {%0,%1,%2,%3};"
        : "+f"(c[0]), "+f"(c[1]), "+f"(c[2]), "+f"(c[3])
        : "r"(a[0]), "r"(a[1]), "r"(a[2]), "r"(a[3]), "r"(b[0]), "r"(b[1]));
}

// ---------------- prep ----------------
// W row r=q*512+hu -> rp = (hu/64)*256 + q*64 + (hu%64)
__global__ void prep_w(const float* __restrict__ Wih, const float* __restrict__ Whh,
                       const float* __restrict__ bih, const float* __restrict__ bhh) {
    int idx = blockIdx.x * blockDim.x + threadIdx.x;
    if (idx >= FOURH * HID) return;
    int r = idx / HID, k = idx - r * HID;
    int q = r >> 9, hu = r & 511;
    int rp = ((hu >> 6) << 8) + (q << 6) + (hu & 63);
    size_t o = (size_t)rp * HID + k;
    float w0 = Wih[idx];
    float ws = w0 + Whh[idx];
    __nv_bfloat16 h0 = __float2bfloat16(w0);
    g_wh0[o] = h0; g_wl0[o] = __float2bfloat16(w0 - __bfloat162float(h0));
    __nv_bfloat16 hs = __float2bfloat16(ws);
    g_wh[o] = hs;  g_wl[o] = __float2bfloat16(ws - __bfloat162float(hs));
    if (k == 0) g_bp[rp] = bih[r] + bhh[r];
}
__global__ void prep_z(const float* __restrict__ z) {
    int i = blockIdx.x * blockDim.x + threadIdx.x;
    if (i >= BSZ * HID) return;
    float v = z[i];
    __nv_bfloat16 h = __float2bfloat16(v);
    g_xh[i] = h;
    g_xl[i] = __float2bfloat16(v - __bfloat162float(h));
}

// ---------------- chunk loader (512 threads, 6 x 16B each) ----------------
__device__ __forceinline__ void issue_chunk(char* stage,
                                            const __nv_bfloat16* Ah, const __nv_bfloat16* Al,
                                            const __nv_bfloat16* Bh, const __nv_bfloat16* Bl,
                                            int k0, int tid) {
    uint32_t sb = smem_u32(stage);
#pragma unroll
    for (int i = 0; i < 2; ++i) {
        int idx = tid + (i << 9);
        const __nv_bfloat16* src = (idx & 512) ? Al : Ah;
        uint32_t toff = (idx & 512) ? AL_OFF : AH_OFF;
        int w = idx & 511, row = w >> 2, q = w & 3;
        cp16(sb + toff + smoff(row, q), src + (size_t)row * HID + k0 + q * 8);
    }
#pragma unroll
    for (int i = 0; i < 4; ++i) {
        int idx = tid + (i << 9);
        const __nv_bfloat16* src = (idx & 1024) ? Bl : Bh;
        uint32_t toff = (idx & 1024) ? BL_OFF : BH_OFF;
        int w = idx & 1023, row = w >> 2, q = w & 3;
        cp16(sb + toff + smoff(row, q), src + (size_t)row * HID + k0 + q * 8);
    }
}

// ---------------- per-step: gates GEMM (3-product bf16 split) + LSTM epilogue ----------------
// 16 warps: wm = warp>>3 (M 2x64), wn = warp&7. Warp wn owns n8-blocks {wn, wn+8, wn+16, wn+24}
// = gates i,f,g,o of hidden units [8wn, 8wn+8): epilogue fully register-local.
__global__ __launch_bounds__(NTHR, 1)
void step_kernel(const __nv_bfloat16* __restrict__ xh, const __nv_bfloat16* __restrict__ xl,
                 const __nv_bfloat16* __restrict__ wh, const __nv_bfloat16* __restrict__ wl,
                 __nv_bfloat16* __restrict__ xh_o, __nv_bfloat16* __restrict__ xl_o,
                 int t0) {
    extern __shared__ char dyn[];
    __shared__ float bias_sm[TN];
    const int tid = threadIdx.x;
    const int lane = tid & 31, warp = tid >> 5;
    const int wm = warp >> 3, wn = warp & 7;
    const int mb = blockIdx.x, nb = blockIdx.y;

    if (tid < TN) bias_sm[tid] = g_bp[nb * TN + tid];

    const __nv_bfloat16* Ah = xh + (size_t)(mb * TM) * HID;
    const __nv_bfloat16* Al = xl + (size_t)(mb * TM) * HID;
    const __nv_bfloat16* Bh = wh + (size_t)(nb * TN) * HID;
    const __nv_bfloat16* Bl = wl + (size_t)(nb * TN) * HID;

    float acc[4][4][4];   // [mi][gate][frag]
#pragma unroll
    for (int mi = 0; mi < 4; ++mi)
#pragma unroll
        for (int g = 0; g < 4; ++g)
#pragma unroll
            for (int r = 0; r < 4; ++r) acc[mi][g][r] = 0.f;

    // precomputed swizzled ldsm offsets (per lane; stage-relative)
    const int a_row = wm * 64 + (lane & 7) + ((lane >> 3) & 1) * 8;
    const int a_q0  = (lane >> 4);
    const int b_row = 8 * (wn + 8 * (lane >> 3)) + (lane & 7);
    uint32_t a_off[4][2], b_off[2][2];
#pragma unroll
    for (int mi = 0; mi < 4; ++mi)
#pragma unroll
        for (int s = 0; s < 2; ++s)
            a_off[mi][s] = smoff(a_row + mi * 16, a_q0 + 2 * s);
#pragma unroll
    for (int s = 0; s < 2; ++s)
#pragma unroll
        for (int k = 0; k < 2; ++k)
            b_off[s][k] = smoff(b_row, 2 * s + k);

    issue_chunk(dyn, Ah, Al, Bh, Bl, 0, tid);
    cp_commit();
    issue_chunk(dyn + STAGE, Ah, Al, Bh, Bl, KC, tid);
    cp_commit();
    issue_chunk(dyn + 2 * STAGE, Ah, Al, Bh, Bl, 2 * KC, tid);
    cp_commit();

#pragma unroll 4
    for (int c = 0; c < NCH; ++c) {
        cp_wait<2>();
        __syncthreads();                 // chunk c resident; prior stage fully drained
        if (c + 3 < NCH)
            issue_chunk(dyn + ((c + 3) & 3) * STAGE, Ah, Al, Bh, Bl, (c + 3) * KC, tid);
        cp_commit();
        uint32_t st = smem_u32(dyn + (c & 3) * STAGE);
#pragma unroll
        for (int s = 0; s < 2; ++s) {
            // ---- pass 1: (Ah + Al) x Bh ----
            uint32_t bh[4][2];
            {
                uint32_t r0[4], r1[4];
                ldsm4(r0, st + BH_OFF + b_off[s][0]);
                ldsm4(r1, st + BH_OFF + b_off[s][1]);
#pragma unroll
                for (int g = 0; g < 4; ++g) { bh[g][0] = r0[g]; bh[g][1] = r1[g]; }
            }
#pragma unroll
            for (int mi = 0; mi < 4; ++mi) {
                uint32_t ah[4], al[4];
                ldsm4(ah, st + AH_OFF + a_off[mi][s]);
#pragma unroll
                for (int g = 0; g < 4; ++g) mma16816(acc[mi][g], ah, bh[g]);
                ldsm4(al, st + AL_OFF + a_off[mi][s]);
#pragma unroll
                for (int g = 0; g < 4; ++g) mma16816(acc[mi][g], al, bh[g]);
            }
            // ---- pass 2: Ah x Bl (Ah reloaded: keeps live-set under the 128-reg cap) ----
            uint32_t bl[4][2];
            {
                uint32_t r0[4], r1[4];
                ldsm4(r0, st + BL_OFF + b_off[s][0]);
                ldsm4(r1, st + BL_OFF + b_off[s][1]);
#pragma unroll
                for (int g = 0; g < 4; ++g) { bl[g][0] = r0[g]; bl[g][1] = r1[g]; }
            }
#pragma unroll
            for (int mi = 0; mi < 4; ++mi) {
                uint32_t ah[4];
                ldsm4(ah, st + AH_OFF + a_off[mi][s]);
#pragma unroll
                for (int g = 0; g < 4; ++g) mma16816(acc[mi][g], ah, bl[g]);
            }
        }
    }

    // ---- fused LSTM epilogue, register-local, vectorized stores ----
    const int gq = lane >> 2, sq = lane & 3;
    const int hu = nb * 64 + 8 * wn + 2 * sq;
#pragma unroll
    for (int mi = 0; mi < 4; ++mi) {
#pragma unroll
        for (int rw = 0; rw < 2; ++rw) {
            int row = mb * TM + wm * 64 + mi * 16 + gq + rw * 8;
            size_t off = (size_t)row * HID + hu;
            float2 cold = t0 ? make_float2(0.f, 0.f) : *(const float2*)(g_c + off);
            float hn[2], cn[2];
#pragma unroll
            for (int e = 0; e < 2; ++e) {
                int r = 2 * rw + e, u = 8 * wn + 2 * sq + e;
                float gi = acc[mi][0][r] + bias_sm[u];
                float gf = acc[mi][1][r] + bias_sm[64 + u];
                float gg = acc[mi][2][r] + bias_sm[128 + u];
                float go = acc[mi][3][r] + bias_sm[192 + u];
                float co = e ? cold.y : cold.x;
                float si = 1.f / (1.f + __expf(-gi));
                float sf = 1.f / (1.f + __expf(-gf));
                float so = 1.f / (1.f + __expf(-go));
                float tg = 2.f / (1.f + __expf(-2.f * gg)) - 1.f;
                cn[e] = fmaf(sf, co, si * tg);
                float tc = 2.f / (1.f + __expf(-2.f * cn[e])) - 1.f;
                hn[e] = so * tc;
            }
            *(float2*)(g_c + off) = make_float2(cn[0], cn[1]);
            __nv_bfloat162 h2, l2;
            h2.x = __float2bfloat16(hn[0]); h2.y = __float2bfloat16(hn[1]);
            l2.x = __float2bfloat16(hn[0] - __bfloat162float(h2.x));
            l2.y = __float2bfloat16(hn[1] - __bfloat162float(h2.y));
            *(__nv_bfloat162*)(xh_o + off) = h2;
            *(__nv_bfloat162*)(xl_o + off) = l2;
        }
    }
}

// ---------------- final projection: all 32 steps in one kernel ----------------
__global__ void out_all(const float* __restrict__ Wd, const float* __restrict__ bd,
                        float* __restrict__ Y) {
    int wg = blockIdx.x * 8 + (threadIdx.x >> 5);
    int lane = threadIdx.x & 31;
    int t = wg & (PH - 1), row = wg >> 5;
    const __nv_bfloat16* xh = g_xh + (size_t)(t + 1) * SLAB + (size_t)row * HID;
    const __nv_bfloat16* xl = g_xl + (size_t)(t + 1) * SLAB + (size_t)row * HID;
    float s0 = 0.f, s1 = 0.f;
    for (int k = lane; k < HID; k += 32) {
        float hv = __bfloat162float(xh[k]) + __bfloat162float(xl[k]);
        s0 = fmaf(hv, Wd[k], s0);
        s1 = fmaf(hv, Wd[HID + k], s1);
    }
#pragma unroll
    for (int o = 16; o > 0; o >>= 1) {
        s0 += __shfl_xor_sync(0xffffffffu, s0, o);
        s1 += __shfl_xor_sync(0xffffffffu, s1, o);
    }
    if (lane == 0) {
        Y[(size_t)row * (PH * 2) + t * 2 + 0] = s0 + bd[0];
        Y[(size_t)row * (PH * 2) + t * 2 + 1] = s1 + bd[1];
    }
}

extern "C" void kernel_launch(void* const* d_in, const int* in_sizes, int n_in,
                              void* d_out, int out_size) {
    // metadata order: hist, z, W_ih, W_hh, b_ih, b_hh, W_d, b_d
    const float* z   = (const float*)d_in[1];
    const float* Wih = (const float*)d_in[2];
    const float* Whh = (const float*)d_in[3];
    const float* bih = (const float*)d_in[4];
    const float* bhh = (const float*)d_in[5];
    const float* Wd  = (const float*)d_in[6];
    const float* bd  = (const float*)d_in[7];
    float* Y = (float*)d_out;

    __nv_bfloat16 *xh, *xl, *wh, *wl, *wh0, *wl0;
    cudaGetSymbolAddress((void**)&xh,  g_xh);
    cudaGetSymbolAddress((void**)&xl,  g_xl);
    cudaGetSymbolAddress((void**)&wh,  g_wh);
    cudaGetSymbolAddress((void**)&wl,  g_wl);
    cudaGetSymbolAddress((void**)&wh0, g_wh0);
    cudaGetSymbolAddress((void**)&wl0, g_wl0);

    cudaFuncSetAttribute(step_kernel, cudaFuncAttributeMaxDynamicSharedMemorySize, SMEM_DYN);

    prep_w<<<(FOURH * HID + 255) / 256, 256>>>(Wih, Whh, bih, bhh);
    prep_z<<<(BSZ * HID + 255) / 256, 256>>>(z);

    dim3 grid(BSZ / TM, FOURH / TN);   // 16 x 8 = 128 CTAs
    for (int t = 0; t < PH; ++t) {
        const __nv_bfloat16* xhi = xh + (size_t)t * SLAB;
        const __nv_bfloat16* xli = xl + (size_t)t * SLAB;
        __nv_bfloat16* xho = xh + (size_t)(t + 1) * SLAB;
        __nv_bfloat16* xlo = xl + (size_t)(t + 1) * SLAB;
        step_kernel<<<grid, NTHR, SMEM_DYN>>>(xhi, xli,
                                              t == 0 ? wh0 : wh, t == 0 ? wl0 : wl,
                                              xho, xlo, t == 0 ? 1 : 0);
    }
    out_all<<<BSZ * PH / 8, 256>>>(Wd, bd, Y);
}

// round 7
// speedup vs baseline: 1.6305x; 1.3345x over previous
#include <cuda_runtime.h>
#include <cuda_fp16.h>
#include <math.h>
#include <stdint.h>

#define HID   512
#define PH    32
#define BSZ   2048
#define FOURH 2048
#define SLAB  (BSZ * HID)

#define TM 128
#define TN 256
#define KC 32
#define NCH (HID / KC)   // 16 k-chunks
#define NTHR 512

// stage layout (bytes): A 128x32 fp16 = 8KB, Bh/Bl 256x32 fp16 = 16KB each
#define AH_OFF 0
#define BH_OFF 8192
#define BL_OFF 24576
#define STAGE  40960
#define NSTG   4
#define SMEM_DYN (NSTG * STAGE)

// ---------------- static device scratch ----------------
__device__ __half g_x[(PH + 1) * (size_t)SLAB];   // x_t (fp16), t=0..PH
__device__ __half g_wh [FOURH * HID];
__device__ __half g_wl [FOURH * HID];
__device__ __half g_wh0[FOURH * HID];
__device__ __half g_wl0[FOURH * HID];
__device__ float g_bp[FOURH];
__device__ float g_c[(size_t)BSZ * HID];

// ---------------- helpers ----------------
__device__ __forceinline__ uint32_t smem_u32(const void* p) {
    uint32_t a;
    asm("{ .reg .u64 t; cvta.to.shared.u64 t, %1; cvt.u32.u64 %0, t; }" : "=r"(a) : "l"(p));
    return a;
}
__device__ __forceinline__ uint32_t smoff(int row, int q) {
    return (uint32_t)((row << 6) + (((q) ^ ((row >> 1) & 3)) << 4));
}
__device__ __forceinline__ void cp16(uint32_t dst, const void* src) {
    asm volatile("cp.async.cg.shared.global [%0], [%1], 16;" :: "r"(dst), "l"(src));
}
__device__ __forceinline__ void cp_commit() { asm volatile("cp.async.commit_group;"); }
template <int N>
__device__ __forceinline__ void cp_wait() {
    asm volatile("cp.async.wait_group %0;" :: "n"(N) : "memory");
}
__device__ __forceinline__ void ldsm4(uint32_t* r, uint32_t addr) {
    asm volatile("ldmatrix.sync.aligned.m8n8.x4.shared.b16 {%0,%1,%2,%3}, [%4];"
        : "=r"(r[0]), "=r"(r[1]), "=r"(r[2]), "=r"(r[3]) : "r"(addr));
}
__device__ __forceinline__ void mma16816(float* c, const uint32_t* a, const uint32_t* b) {
    asm volatile(
        "mma.sync.aligned.m16n8k16.row.col.f32.f16.f16.f32 "
        "{%0,%1,%2,%3}, {%4,%5,%6,%7}, {%8,%9}, {%0,%1,%2,%3};"
        : "+f"(c[0]), "+f"(c[1]), "+f"(c[2]), "+f"(c[3])
        : "r"(a[0]), "r"(a[1]), "r"(a[2]), "r"(a[3]), "r"(b[0]), "r"(b[1]));
}

// ---------------- prep ----------------
// W row r=q*512+hu -> rp = (hu/64)*256 + q*64 + (hu%64)
__global__ void prep_w(const float* __restrict__ Wih, const float* __restrict__ Whh,
                       const float* __restrict__ bih, const float* __restrict__ bhh) {
    int idx = blockIdx.x * blockDim.x + threadIdx.x;
    if (idx >= FOURH * HID) return;
    int r = idx / HID, k = idx - r * HID;
    int q = r >> 9, hu = r & 511;
    int rp = ((hu >> 6) << 8) + (q << 6) + (hu & 63);
    size_t o = (size_t)rp * HID + k;
    float w0 = Wih[idx];
    float ws = w0 + Whh[idx];
    __half h0 = __float2half_rn(w0);
    g_wh0[o] = h0; g_wl0[o] = __float2half_rn(w0 - __half2float(h0));
    __half hs = __float2half_rn(ws);
    g_wh[o] = hs;  g_wl[o] = __float2half_rn(ws - __half2float(hs));
    if (k == 0) g_bp[rp] = bih[r] + bhh[r];
}
__global__ void prep_z(const float* __restrict__ z) {
    int i = blockIdx.x * blockDim.x + threadIdx.x;
    if (i >= BSZ * HID) return;
    g_x[i] = __float2half_rn(z[i]);
}

// ---------------- per-step: gates = X @ (Wh+Wl)^T via 2-product fp16 + LSTM epilogue ------
// 16 warps: wm = warp>>3 (M 2x64), wn = warp&7. Warp wn owns n8-blocks {wn, wn+8, wn+16,
// wn+24} = gates i,f,g,o of hidden units [8wn, 8wn+8): epilogue fully register-local.
__global__ __launch_bounds__(NTHR, 1)
void step_kernel(const __half* __restrict__ x, const __half* __restrict__ wh,
                 const __half* __restrict__ wl, __half* __restrict__ x_o, int t0) {
    extern __shared__ char dyn[];
    __shared__ float bias_sm[TN];
    const int tid = threadIdx.x;
    const int lane = tid & 31, warp = tid >> 5;
    const int wm = warp >> 3, wn = warp & 7;
    const int mb = blockIdx.x, nb = blockIdx.y;

    if (tid < TN) bias_sm[tid] = g_bp[nb * TN + tid];

    const __half* A = x + (size_t)(mb * TM) * HID;
    const __half* Bh = wh + (size_t)(nb * TN) * HID;
    const __half* Bl = wl + (size_t)(nb * TN) * HID;

    // ---- hoisted cp.async plan: 1 A quad + 4 B quads per thread ----
    const __half* a_src;
    uint32_t a_dst;
    {
        int row = tid >> 2, q = tid & 3;
        a_src = A + (size_t)row * HID + q * 8;
        a_dst = AH_OFF + smoff(row, q);
    }
    const __half* b_src[4];
    uint32_t b_dst[4];
#pragma unroll
    for (int i = 0; i < 4; ++i) {
        int idx = tid + (i << 9);
        int w = idx & 1023, row = w >> 2, q = w & 3;
        b_src[i] = ((idx & 1024) ? Bl : Bh) + (size_t)row * HID + q * 8;
        b_dst[i] = ((idx & 1024) ? BL_OFF : BH_OFF) + smoff(row, q);
    }

    float acc[4][4][4];   // [mi][gate][frag]
#pragma unroll
    for (int mi = 0; mi < 4; ++mi)
#pragma unroll
        for (int g = 0; g < 4; ++g)
#pragma unroll
            for (int r = 0; r < 4; ++r) acc[mi][g][r] = 0.f;

    // precomputed swizzled ldsm offsets
    const int a_row = wm * 64 + (lane & 7) + ((lane >> 3) & 1) * 8;
    const int a_q0  = (lane >> 4);
    const int b_row = 8 * (wn + 8 * (lane >> 3)) + (lane & 7);
    uint32_t a_off[4][2], b_off[2][2];
#pragma unroll
    for (int mi = 0; mi < 4; ++mi)
#pragma unroll
        for (int s = 0; s < 2; ++s)
            a_off[mi][s] = smoff(a_row + mi * 16, a_q0 + 2 * s);
#pragma unroll
    for (int s = 0; s < 2; ++s)
#pragma unroll
        for (int k = 0; k < 2; ++k)
            b_off[s][k] = smoff(b_row, 2 * s + k);

#pragma unroll
    for (int p = 0; p < 3; ++p) {
        uint32_t sb = smem_u32(dyn + p * STAGE);
        int k0 = p * KC;
        cp16(sb + a_dst, a_src + k0);
#pragma unroll
        for (int i = 0; i < 4; ++i) cp16(sb + b_dst[i], b_src[i] + k0);
        cp_commit();
    }

#pragma unroll 4
    for (int c = 0; c < NCH; ++c) {
        cp_wait<2>();
        __syncthreads();                 // chunk c resident; prior stage fully drained
        if (c + 3 < NCH) {
            uint32_t sb = smem_u32(dyn + ((c + 3) & 3) * STAGE);
            int k0 = (c + 3) * KC;
            cp16(sb + a_dst, a_src + k0);
#pragma unroll
            for (int i = 0; i < 4; ++i) cp16(sb + b_dst[i], b_src[i] + k0);
        }
        cp_commit();
        uint32_t st = smem_u32(dyn + (c & 3) * STAGE);
#pragma unroll
        for (int s = 0; s < 2; ++s) {
            uint32_t bh[4][2], bl[4][2];
            {
                uint32_t r0[4], r1[4];
                ldsm4(r0, st + BH_OFF + b_off[s][0]);
                ldsm4(r1, st + BH_OFF + b_off[s][1]);
#pragma unroll
                for (int g = 0; g < 4; ++g) { bh[g][0] = r0[g]; bh[g][1] = r1[g]; }
                ldsm4(r0, st + BL_OFF + b_off[s][0]);
                ldsm4(r1, st + BL_OFF + b_off[s][1]);
#pragma unroll
                for (int g = 0; g < 4; ++g) { bl[g][0] = r0[g]; bl[g][1] = r1[g]; }
            }
#pragma unroll
            for (int mi = 0; mi < 4; ++mi) {
                uint32_t ah[4];
                ldsm4(ah, st + AH_OFF + a_off[mi][s]);
#pragma unroll
                for (int g = 0; g < 4; ++g) mma16816(acc[mi][g], ah, bh[g]);
#pragma unroll
                for (int g = 0; g < 4; ++g) mma16816(acc[mi][g], ah, bl[g]);
            }
        }
    }

    // ---- fused LSTM epilogue, register-local, vectorized stores ----
    const int gq = lane >> 2, sq = lane & 3;
    const int hu = nb * 64 + 8 * wn + 2 * sq;
#pragma unroll
    for (int mi = 0; mi < 4; ++mi) {
#pragma unroll
        for (int rw = 0; rw < 2; ++rw) {
            int row = mb * TM + wm * 64 + mi * 16 + gq + rw * 8;
            size_t off = (size_t)row * HID + hu;
            float2 cold = t0 ? make_float2(0.f, 0.f) : *(const float2*)(g_c + off);
            float hn[2], cn[2];
#pragma unroll
            for (int e = 0; e < 2; ++e) {
                int r = 2 * rw + e, u = 8 * wn + 2 * sq + e;
                float gi = acc[mi][0][r] + bias_sm[u];
                float gf = acc[mi][1][r] + bias_sm[64 + u];
                float gg = acc[mi][2][r] + bias_sm[128 + u];
                float go = acc[mi][3][r] + bias_sm[192 + u];
                float co = e ? cold.y : cold.x;
                float si = 1.f / (1.f + __expf(-gi));
                float sf = 1.f / (1.f + __expf(-gf));
                float so = 1.f / (1.f + __expf(-go));
                float tg = 2.f / (1.f + __expf(-2.f * gg)) - 1.f;
                cn[e] = fmaf(sf, co, si * tg);
                float tc = 2.f / (1.f + __expf(-2.f * cn[e])) - 1.f;
                hn[e] = so * tc;
            }
            *(float2*)(g_c + off) = make_float2(cn[0], cn[1]);
            __half2 h2;
            h2.x = __float2half_rn(hn[0]); h2.y = __float2half_rn(hn[1]);
            *(__half2*)(x_o + off) = h2;
        }
    }
}

// ---------------- final projection: all 32 steps in one kernel ----------------
__global__ void out_all(const float* __restrict__ Wd, const float* __restrict__ bd,
                        float* __restrict__ Y) {
    int wg = blockIdx.x * 8 + (threadIdx.x >> 5);
    int lane = threadIdx.x & 31;
    int t = wg & (PH - 1), row = wg >> 5;
    const __half* xp = g_x + (size_t)(t + 1) * SLAB + (size_t)row * HID;
    float s0 = 0.f, s1 = 0.f;
    for (int k = lane; k < HID; k += 32) {
        float hv = __half2float(xp[k]);
        s0 = fmaf(hv, Wd[k], s0);
        s1 = fmaf(hv, Wd[HID + k], s1);
    }
#pragma unroll
    for (int o = 16; o > 0; o >>= 1) {
        s0 += __shfl_xor_sync(0xffffffffu, s0, o);
        s1 += __shfl_xor_sync(0xffffffffu, s1, o);
    }
    if (lane == 0) {
        Y[(size_t)row * (PH * 2) + t * 2 + 0] = s0 + bd[0];
        Y[(size_t)row * (PH * 2) + t * 2 + 1] = s1 + bd[1];
    }
}

extern "C" void kernel_launch(void* const* d_in, const int* in_sizes, int n_in,
                              void* d_out, int out_size) {
    // metadata order: hist, z, W_ih, W_hh, b_ih, b_hh, W_d, b_d
    const float* z   = (const float*)d_in[1];
    const float* Wih = (const float*)d_in[2];
    const float* Whh = (const float*)d_in[3];
    const float* bih = (const float*)d_in[4];
    const float* bhh = (const float*)d_in[5];
    const float* Wd  = (const float*)d_in[6];
    const float* bd  = (const float*)d_in[7];
    float* Y = (float*)d_out;

    __half *xp, *wh, *wl, *wh0, *wl0;
    cudaGetSymbolAddress((void**)&xp,  g_x);
    cudaGetSymbolAddress((void**)&wh,  g_wh);
    cudaGetSymbolAddress((void**)&wl,  g_wl);
    cudaGetSymbolAddress((void**)&wh0, g_wh0);
    cudaGetSymbolAddress((void**)&wl0, g_wl0);

    cudaFuncSetAttribute(step_kernel, cudaFuncAttributeMaxDynamicSharedMemorySize, SMEM_DYN);

    prep_w<<<(FOURH * HID + 255) / 256, 256>>>(Wih, Whh, bih, bhh);
    prep_z<<<(BSZ * HID + 255) / 256, 256>>>(z);

    dim3 grid(BSZ / TM, FOURH / TN);   // 16 x 8 = 128 CTAs
    for (int t = 0; t < PH; ++t) {
        step_kernel<<<grid, NTHR, SMEM_DYN>>>(xp + (size_t)t * SLAB,
                                              t == 0 ? wh0 : wh, t == 0 ? wl0 : wl,
                                              xp + (size_t)(t + 1) * SLAB, t == 0 ? 1 : 0);
    }
    out_all<<<BSZ * PH / 8, 256>>>(Wd, bd, Y);
}

// round 8
// speedup vs baseline: 1.7102x; 1.0489x over previous
#include <cuda_runtime.h>
#include <cuda_fp16.h>
#include <math.h>
#include <stdint.h>

#define HID   512
#define PH    32
#define BSZ   2048
#define FOURH 2048
#define SLAB  (BSZ * HID)
#define WHALF (FOURH * HID)      // element offset of lo-slab inside merged W array

#define TM 128
#define TN 128
#define KC 32
#define NCH (HID / KC)   // 16 k-chunks
#define NTHR 256

// stage layout (bytes): A 128x32 fp16 = 8KB, Bh 8KB, Bl 8KB
#define AH_OFF 0
#define BH_OFF 8192
#define BL_OFF 16384
#define STAGE  24576
#define NSTG   4
#define SMEM_DYN (NSTG * STAGE)   // 96KB -> 2 CTAs/SM

// ---------------- static device scratch ----------------
__device__ __half g_x[(PH + 1) * (size_t)SLAB];   // x_t (fp16), t=0..PH
__device__ __half g_wA [2 * WHALF];   // [hi | lo] of (W_ih + W_hh), permuted
__device__ __half g_wA0[2 * WHALF];   // [hi | lo] of W_ih, permuted (step 0)
__device__ float g_bp[FOURH];
__device__ float g_c[(size_t)BSZ * HID];

// ---------------- helpers ----------------
__device__ __forceinline__ uint32_t smem_u32(const void* p) {
    uint32_t a;
    asm("{ .reg .u64 t; cvta.to.shared.u64 t, %1; cvt.u32.u64 %0, t; }" : "=r"(a) : "l"(p));
    return a;
}
__device__ __forceinline__ uint32_t smoff(int row, int q) {
    return (uint32_t)((row << 6) + (((q) ^ ((row >> 1) & 3)) << 4));
}
__device__ __forceinline__ void cp16(uint32_t dst, const void* src) {
    asm volatile("cp.async.cg.shared.global [%0], [%1], 16;" :: "r"(dst), "l"(src));
}
__device__ __forceinline__ void cp_commit() { asm volatile("cp.async.commit_group;"); }
template <int N>
__device__ __forceinline__ void cp_wait() {
    asm volatile("cp.async.wait_group %0;" :: "n"(N) : "memory");
}
__device__ __forceinline__ void ldsm4(uint32_t* r, uint32_t addr) {
    asm volatile("ldmatrix.sync.aligned.m8n8.x4.shared.b16 {%0,%1,%2,%3}, [%4];"
        : "=r"(r[0]), "=r"(r[1]), "=r"(r[2]), "=r"(r[3]) : "r"(addr));
}
__device__ __forceinline__ void mma16816(float* c, const uint32_t* a, const uint32_t* b) {
    asm volatile(
        "mma.sync.aligned.m16n8k16.row.col.f32.f16.f16.f32 "
        "{%0,%1,%2,%3}, {%4,%5,%6,%7}, {%8,%9}, {%0,%1,%2,%3};"
        : "+f"(c[0]), "+f"(c[1]), "+f"(c[2]), "+f"(c[3])
        : "r"(a[0]), "r"(a[1]), "r"(a[2]), "r"(a[3]), "r"(b[0]), "r"(b[1]));
}

// ---------------- prep ----------------
// W row r=q*512+hu -> rp = (hu/32)*128 + q*32 + (hu%32): N-tile nb holds 32 units x 4 gates
__global__ void prep_w(const float* __restrict__ Wih, const float* __restrict__ Whh,
                       const float* __restrict__ bih, const float* __restrict__ bhh) {
    int idx = blockIdx.x * blockDim.x + threadIdx.x;
    if (idx >= FOURH * HID) return;
    int r = idx / HID, k = idx - r * HID;
    int q = r >> 9, hu = r & 511;
    int rp = ((hu >> 5) << 7) + (q << 5) + (hu & 31);
    size_t o = (size_t)rp * HID + k;
    float w0 = Wih[idx];
    float ws = w0 + Whh[idx];
    __half h0 = __float2half_rn(w0);
    g_wA0[o] = h0; g_wA0[WHALF + o] = __float2half_rn(w0 - __half2float(h0));
    __half hs = __float2half_rn(ws);
    g_wA[o] = hs;  g_wA[WHALF + o] = __float2half_rn(ws - __half2float(hs));
    if (k == 0) g_bp[rp] = bih[r] + bhh[r];
}
__global__ void prep_z(const float* __restrict__ z) {
    int i = blockIdx.x * blockDim.x + threadIdx.x;
    if (i >= BSZ * HID) return;
    g_x[i] = __float2half_rn(z[i]);
}

// ---------------- per-step: gates = X @ (Wh+Wl)^T (2-product fp16) + LSTM epilogue ----
// 8 warps: wm = warp>>2 (M 2x64), wn = warp&3. Warp wn owns n8-blocks {wn, wn+4, wn+8,
// wn+12} = gates i,f,g,o of hidden units [8wn, 8wn+8): epilogue fully register-local.
__global__ __launch_bounds__(NTHR, 2)
void step_kernel(const __half* __restrict__ x, const __half* __restrict__ w,
                 __half* __restrict__ x_o, int t0) {
    extern __shared__ char dyn[];
    __shared__ float bias_sm[TN];
    const int tid = threadIdx.x;
    const int lane = tid & 31, warp = tid >> 5;
    const int wm = warp >> 2, wn = warp & 3;
    const int mb = blockIdx.x, nb = blockIdx.y;

    if (tid < TN) bias_sm[tid] = g_bp[nb * TN + tid];

    // ---- cp.async plan: single base src/dst per operand, constant strides ----
    const int lrow = tid >> 2, lq = tid & 3;           // row 0..63, quad 0..3
    const __half* a_src = x + (size_t)(mb * TM + lrow) * HID + lq * 8;
    const __half* b_src = w + (size_t)(nb * TN + lrow) * HID + lq * 8;
    const uint32_t a_dst0 = AH_OFF + smoff(lrow, lq);  // +4096 per 64 rows
    const uint32_t b_dst0 = BH_OFF + smoff(lrow, lq);

    float acc[4][4][4];   // [mi][gate][frag]
#pragma unroll
    for (int mi = 0; mi < 4; ++mi)
#pragma unroll
        for (int g = 0; g < 4; ++g)
#pragma unroll
            for (int r = 0; r < 4; ++r) acc[mi][g][r] = 0.f;

    // precomputed swizzled ldsm offsets
    const int a_row = wm * 64 + (lane & 7) + ((lane >> 3) & 1) * 8;
    const int a_q0  = (lane >> 4);
    const int b_row = 8 * (4 * (lane >> 3) + wn) + (lane & 7);   // n8 block = g*4 + wn
    uint32_t a_off[4][2], b_off[2][2];
#pragma unroll
    for (int mi = 0; mi < 4; ++mi)
#pragma unroll
        for (int s = 0; s < 2; ++s)
            a_off[mi][s] = smoff(a_row + mi * 16, a_q0 + 2 * s);
#pragma unroll
    for (int s = 0; s < 2; ++s)
#pragma unroll
        for (int k = 0; k < 2; ++k)
            b_off[s][k] = smoff(b_row, 2 * s + k);

#pragma unroll
    for (int p = 0; p < 3; ++p) {
        uint32_t sb = smem_u32(dyn + p * STAGE);
        int k0 = p * KC;
        cp16(sb + a_dst0,        a_src + k0);
        cp16(sb + a_dst0 + 4096, a_src + 64 * HID + k0);
        cp16(sb + b_dst0,        b_src + k0);
        cp16(sb + b_dst0 + 4096, b_src + 64 * HID + k0);
        cp16(sb + b_dst0 + (BL_OFF - BH_OFF),        b_src + WHALF + k0);
        cp16(sb + b_dst0 + (BL_OFF - BH_OFF) + 4096, b_src + WHALF + 64 * HID + k0);
        cp_commit();
    }

#pragma unroll 4
    for (int c = 0; c < NCH; ++c) {
        cp_wait<2>();
        __syncthreads();                 // chunk c resident; prior stage fully drained
        if (c + 3 < NCH) {
            uint32_t sb = smem_u32(dyn + ((c + 3) & 3) * STAGE);
            int k0 = (c + 3) * KC;
            cp16(sb + a_dst0,        a_src + k0);
            cp16(sb + a_dst0 + 4096, a_src + 64 * HID + k0);
            cp16(sb + b_dst0,        b_src + k0);
            cp16(sb + b_dst0 + 4096, b_src + 64 * HID + k0);
            cp16(sb + b_dst0 + (BL_OFF - BH_OFF),        b_src + WHALF + k0);
            cp16(sb + b_dst0 + (BL_OFF - BH_OFF) + 4096, b_src + WHALF + 64 * HID + k0);
        }
        cp_commit();
        uint32_t st = smem_u32(dyn + (c & 3) * STAGE);
#pragma unroll
        for (int s = 0; s < 2; ++s) {
            uint32_t bh[4][2], bl[4][2];
            {
                uint32_t r0[4], r1[4];
                ldsm4(r0, st + BH_OFF + b_off[s][0]);
                ldsm4(r1, st + BH_OFF + b_off[s][1]);
#pragma unroll
                for (int g = 0; g < 4; ++g) { bh[g][0] = r0[g]; bh[g][1] = r1[g]; }
                ldsm4(r0, st + BL_OFF + b_off[s][0]);
                ldsm4(r1, st + BL_OFF + b_off[s][1]);
#pragma unroll
                for (int g = 0; g < 4; ++g) { bl[g][0] = r0[g]; bl[g][1] = r1[g]; }
            }
#pragma unroll
            for (int mi = 0; mi < 4; ++mi) {
                uint32_t ah[4];
                ldsm4(ah, st + AH_OFF + a_off[mi][s]);
#pragma unroll
                for (int g = 0; g < 4; ++g) mma16816(acc[mi][g], ah, bh[g]);
#pragma unroll
                for (int g = 0; g < 4; ++g) mma16816(acc[mi][g], ah, bl[g]);
            }
        }
    }

    // ---- fused LSTM epilogue, register-local, vectorized stores ----
    const int gq = lane >> 2, sq = lane & 3;
    const int hu = nb * 32 + 8 * wn + 2 * sq;
#pragma unroll
    for (int mi = 0; mi < 4; ++mi) {
#pragma unroll
        for (int rw = 0; rw < 2; ++rw) {
            int row = mb * TM + wm * 64 + mi * 16 + gq + rw * 8;
            size_t off = (size_t)row * HID + hu;
            float2 cold = t0 ? make_float2(0.f, 0.f) : *(const float2*)(g_c + off);
            float hn[2], cn[2];
#pragma unroll
            for (int e = 0; e < 2; ++e) {
                int r = 2 * rw + e, u = 8 * wn + 2 * sq + e;
                float gi = acc[mi][0][r] + bias_sm[u];
                float gf = acc[mi][1][r] + bias_sm[32 + u];
                float gg = acc[mi][2][r] + bias_sm[64 + u];
                float go = acc[mi][3][r] + bias_sm[96 + u];
                float co = e ? cold.y : cold.x;
                float si = 1.f / (1.f + __expf(-gi));
                float sf = 1.f / (1.f + __expf(-gf));
                float so = 1.f / (1.f + __expf(-go));
                float tg = 2.f / (1.f + __expf(-2.f * gg)) - 1.f;
                cn[e] = fmaf(sf, co, si * tg);
                float tc = 2.f / (1.f + __expf(-2.f * cn[e])) - 1.f;
                hn[e] = so * tc;
            }
            *(float2*)(g_c + off) = make_float2(cn[0], cn[1]);
            __half2 h2;
            h2.x = __float2half_rn(hn[0]); h2.y = __float2half_rn(hn[1]);
            *(__half2*)(x_o + off) = h2;
        }
    }
}

// ---------------- final projection: all 32 steps in one kernel ----------------
__global__ void out_all(const float* __restrict__ Wd, const float* __restrict__ bd,
                        float* __restrict__ Y) {
    int wg = blockIdx.x * 8 + (threadIdx.x >> 5);
    int lane = threadIdx.x & 31;
    int t = wg & (PH - 1), row = wg >> 5;
    const __half* xp = g_x + (size_t)(t + 1) * SLAB + (size_t)row * HID;
    float s0 = 0.f, s1 = 0.f;
    for (int k = lane; k < HID; k += 32) {
        float hv = __half2float(xp[k]);
        s0 = fmaf(hv, Wd[k], s0);
        s1 = fmaf(hv, Wd[HID + k], s1);
    }
#pragma unroll
    for (int o = 16; o > 0; o >>= 1) {
        s0 += __shfl_xor_sync(0xffffffffu, s0, o);
        s1 += __shfl_xor_sync(0xffffffffu, s1, o);
    }
    if (lane == 0) {
        Y[(size_t)row * (PH * 2) + t * 2 + 0] = s0 + bd[0];
        Y[(size_t)row * (PH * 2) + t * 2 + 1] = s1 + bd[1];
    }
}

extern "C" void kernel_launch(void* const* d_in, const int* in_sizes, int n_in,
                              void* d_out, int out_size) {
    // metadata order: hist, z, W_ih, W_hh, b_ih, b_hh, W_d, b_d
    const float* z   = (const float*)d_in[1];
    const float* Wih = (const float*)d_in[2];
    const float* Whh = (const float*)d_in[3];
    const float* bih = (const float*)d_in[4];
    const float* bhh = (const float*)d_in[5];
    const float* Wd  = (const float*)d_in[6];
    const float* bd  = (const float*)d_in[7];
    float* Y = (float*)d_out;

    __half *xp, *wA, *wA0;
    cudaGetSymbolAddress((void**)&xp,  g_x);
    cudaGetSymbolAddress((void**)&wA,  g_wA);
    cudaGetSymbolAddress((void**)&wA0, g_wA0);

    cudaFuncSetAttribute(step_kernel, cudaFuncAttributeMaxDynamicSharedMemorySize, SMEM_DYN);

    prep_w<<<(FOURH * HID + 255) / 256, 256>>>(Wih, Whh, bih, bhh);
    prep_z<<<(BSZ * HID + 255) / 256, 256>>>(z);

    dim3 grid(BSZ / TM, FOURH / TN);   // 16 x 16 = 256 CTAs, 2 per SM
    for (int t = 0; t < PH; ++t) {
        step_kernel<<<grid, NTHR, SMEM_DYN>>>(xp + (size_t)t * SLAB,
                                              t == 0 ? wA0 : wA,
                                              xp + (size_t)(t + 1) * SLAB, t == 0 ? 1 : 0);
    }
    out_all<<<BSZ * PH / 8, 256>>>(Wd, bd, Y);
}

// round 9
// speedup vs baseline: 2.5784x; 1.5077x over previous
#include <cuda_runtime.h>
#include <cuda_fp16.h>
#include <math.h>
#include <stdint.h>

#define HID   512
#define PH    32
#define BSZ   2048
#define FOURH 2048
#define SLAB  (BSZ * HID)

#define TM 128
#define TN 128
#define KC 32
#define NCH (HID / KC)   // 16 k-chunks
#define NTHR 256

// stage layout (bytes): A 128x32 fp16 = 8KB, B 128x32 fp16 = 8KB
#define AH_OFF 0
#define BH_OFF 8192
#define STAGE  16384
#define NSTG   4
#define SMEM_DYN (NSTG * STAGE)   // 64KB -> 2 CTAs/SM

// ---------------- static device scratch ----------------
__device__ __half g_x[(PH + 1) * (size_t)SLAB];   // x_t (fp16), t=0..PH
__device__ __half g_w [FOURH * HID];   // fp16(W_ih + W_hh), permuted
__device__ __half g_w0[FOURH * HID];   // fp16(W_ih), permuted (step 0)
__device__ float g_bp[FOURH];
__device__ float g_c[(size_t)BSZ * HID];

// ---------------- helpers ----------------
__device__ __forceinline__ uint32_t smem_u32(const void* p) {
    uint32_t a;
    asm("{ .reg .u64 t; cvta.to.shared.u64 t, %1; cvt.u32.u64 %0, t; }" : "=r"(a) : "l"(p));
    return a;
}
__device__ __forceinline__ uint32_t smoff(int row, int q) {
    return (uint32_t)((row << 6) + (((q) ^ ((row >> 1) & 3)) << 4));
}
__device__ __forceinline__ void cp16(uint32_t dst, const void* src) {
    asm volatile("cp.async.cg.shared.global [%0], [%1], 16;" :: "r"(dst), "l"(src));
}
__device__ __forceinline__ void cp_commit() { asm volatile("cp.async.commit_group;"); }
template <int N>
__device__ __forceinline__ void cp_wait() {
    asm volatile("cp.async.wait_group %0;" :: "n"(N) : "memory");
}
__device__ __forceinline__ void ldsm4(uint32_t* r, uint32_t addr) {
    asm volatile("ldmatrix.sync.aligned.m8n8.x4.shared.b16 {%0,%1,%2,%3}, [%4];"
        : "=r"(r[0]), "=r"(r[1]), "=r"(r[2]), "=r"(r[3]) : "r"(addr));
}
__device__ __forceinline__ void mma16816(float* c, const uint32_t* a, const uint32_t* b) {
    asm volatile(
        "mma.sync.aligned.m16n8k16.row.col.f32.f16.f16.f32 "
        "{%0,%1,%2,%3}, {%4,%5,%6,%7}, {%8,%9}, {%0,%1,%2,%3};"
        : "+f"(c[0]), "+f"(c[1]), "+f"(c[2]), "+f"(c[3])
        : "r"(a[0]), "r"(a[1]), "r"(a[2]), "r"(a[3]), "r"(b[0]), "r"(b[1]));
}

// ---------------- prep ----------------
// W row r=q*512+hu -> rp = (hu/32)*128 + q*32 + (hu%32): N-tile nb holds 32 units x 4 gates
__global__ void prep_w(const float* __restrict__ Wih, const float* __restrict__ Whh,
                       const float* __restrict__ bih, const float* __restrict__ bhh) {
    int idx = blockIdx.x * blockDim.x + threadIdx.x;
    if (idx >= FOURH * HID) return;
    int r = idx / HID, k = idx - r * HID;
    int q = r >> 9, hu = r & 511;
    int rp = ((hu >> 5) << 7) + (q << 5) + (hu & 31);
    size_t o = (size_t)rp * HID + k;
    g_w0[o] = __float2half_rn(Wih[idx]);
    g_w [o] = __float2half_rn(Wih[idx] + Whh[idx]);
    if (k == 0) g_bp[rp] = bih[r] + bhh[r];
}
__global__ void prep_z(const float* __restrict__ z) {
    int i = blockIdx.x * blockDim.x + threadIdx.x;
    if (i >= BSZ * HID) return;
    g_x[i] = __float2half_rn(z[i]);
}

// ---------------- per-step: gates = X @ W^T (single-product fp16) + LSTM epilogue ----
// 8 warps: wm = warp>>2 (M 2x64), wn = warp&3. Warp wn owns n8-blocks {wn, wn+4, wn+8,
// wn+12} = gates i,f,g,o of hidden units [8wn, 8wn+8): epilogue fully register-local.
__global__ __launch_bounds__(NTHR, 2)
void step_kernel(const __half* __restrict__ x, const __half* __restrict__ w,
                 __half* __restrict__ x_o, int t0) {
    extern __shared__ char dyn[];
    __shared__ float bias_sm[TN];
    const int tid = threadIdx.x;
    const int lane = tid & 31, warp = tid >> 5;
    const int wm = warp >> 2, wn = warp & 3;
    const int mb = blockIdx.x, nb = blockIdx.y;

    if (tid < TN) bias_sm[tid] = g_bp[nb * TN + tid];

    // ---- cp.async plan: single base src/dst per operand, constant strides ----
    const int lrow = tid >> 2, lq = tid & 3;           // row 0..63, quad 0..3
    const __half* a_src = x + (size_t)(mb * TM + lrow) * HID + lq * 8;
    const __half* b_src = w + (size_t)(nb * TN + lrow) * HID + lq * 8;
    const uint32_t a_dst0 = AH_OFF + smoff(lrow, lq);  // +4096 per 64 rows
    const uint32_t b_dst0 = BH_OFF + smoff(lrow, lq);

    float acc[4][4][4];   // [mi][gate][frag]
#pragma unroll
    for (int mi = 0; mi < 4; ++mi)
#pragma unroll
        for (int g = 0; g < 4; ++g)
#pragma unroll
            for (int r = 0; r < 4; ++r) acc[mi][g][r] = 0.f;

    // precomputed swizzled ldsm offsets
    const int a_row = wm * 64 + (lane & 7) + ((lane >> 3) & 1) * 8;
    const int a_q0  = (lane >> 4);
    const int b_row = 8 * (4 * (lane >> 3) + wn) + (lane & 7);   // n8 block = g*4 + wn
    uint32_t a_off[4][2], b_off[2][2];
#pragma unroll
    for (int mi = 0; mi < 4; ++mi)
#pragma unroll
        for (int s = 0; s < 2; ++s)
            a_off[mi][s] = smoff(a_row + mi * 16, a_q0 + 2 * s);
#pragma unroll
    for (int s = 0; s < 2; ++s)
#pragma unroll
        for (int k = 0; k < 2; ++k)
            b_off[s][k] = smoff(b_row, 2 * s + k);

#pragma unroll
    for (int p = 0; p < 3; ++p) {
        uint32_t sb = smem_u32(dyn + p * STAGE);
        int k0 = p * KC;
        cp16(sb + a_dst0,        a_src + k0);
        cp16(sb + a_dst0 + 4096, a_src + 64 * HID + k0);
        cp16(sb + b_dst0,        b_src + k0);
        cp16(sb + b_dst0 + 4096, b_src + 64 * HID + k0);
        cp_commit();
    }

#pragma unroll 4
    for (int c = 0; c < NCH; ++c) {
        cp_wait<2>();
        __syncthreads();                 // chunk c resident; prior stage fully drained
        if (c + 3 < NCH) {
            uint32_t sb = smem_u32(dyn + ((c + 3) & 3) * STAGE);
            int k0 = (c + 3) * KC;
            cp16(sb + a_dst0,        a_src + k0);
            cp16(sb + a_dst0 + 4096, a_src + 64 * HID + k0);
            cp16(sb + b_dst0,        b_src + k0);
            cp16(sb + b_dst0 + 4096, b_src + 64 * HID + k0);
        }
        cp_commit();
        uint32_t st = smem_u32(dyn + (c & 3) * STAGE);
#pragma unroll
        for (int s = 0; s < 2; ++s) {
            uint32_t bh[4][2];
            {
                uint32_t r0[4], r1[4];
                ldsm4(r0, st + BH_OFF + b_off[s][0]);
                ldsm4(r1, st + BH_OFF + b_off[s][1]);
#pragma unroll
                for (int g = 0; g < 4; ++g) { bh[g][0] = r0[g]; bh[g][1] = r1[g]; }
            }
#pragma unroll
            for (int mi = 0; mi < 4; ++mi) {
                uint32_t ah[4];
                ldsm4(ah, st + AH_OFF + a_off[mi][s]);
#pragma unroll
                for (int g = 0; g < 4; ++g) mma16816(acc[mi][g], ah, bh[g]);
            }
        }
    }

    // ---- fused LSTM epilogue, register-local, vectorized stores ----
    const int gq = lane >> 2, sq = lane & 3;
    const int hu = nb * 32 + 8 * wn + 2 * sq;
#pragma unroll
    for (int mi = 0; mi < 4; ++mi) {
#pragma unroll
        for (int rw = 0; rw < 2; ++rw) {
            int row = mb * TM + wm * 64 + mi * 16 + gq + rw * 8;
            size_t off = (size_t)row * HID + hu;
            float2 cold = t0 ? make_float2(0.f, 0.f) : *(const float2*)(g_c + off);
            float hn[2], cn[2];
#pragma unroll
            for (int e = 0; e < 2; ++e) {
                int r = 2 * rw + e, u = 8 * wn + 2 * sq + e;
                float gi = acc[mi][0][r] + bias_sm[u];
                float gf = acc[mi][1][r] + bias_sm[32 + u];
                float gg = acc[mi][2][r] + bias_sm[64 + u];
                float go = acc[mi][3][r] + bias_sm[96 + u];
                float co = e ? cold.y : cold.x;
                float si = 1.f / (1.f + __expf(-gi));
                float sf = 1.f / (1.f + __expf(-gf));
                float so = 1.f / (1.f + __expf(-go));
                float tg = 2.f / (1.f + __expf(-2.f * gg)) - 1.f;
                cn[e] = fmaf(sf, co, si * tg);
                float tc = 2.f / (1.f + __expf(-2.f * cn[e])) - 1.f;
                hn[e] = so * tc;
            }
            *(float2*)(g_c + off) = make_float2(cn[0], cn[1]);
            __half2 h2;
            h2.x = __float2half_rn(hn[0]); h2.y = __float2half_rn(hn[1]);
            *(__half2*)(x_o + off) = h2;
        }
    }
}

// ---------------- final projection: all 32 steps in one kernel ----------------
__global__ void out_all(const float* __restrict__ Wd, const float* __restrict__ bd,
                        float* __restrict__ Y) {
    int wg = blockIdx.x * 8 + (threadIdx.x >> 5);
    int lane = threadIdx.x & 31;
    int t = wg & (PH - 1), row = wg >> 5;
    const __half* xp = g_x + (size_t)(t + 1) * SLAB + (size_t)row * HID;
    float s0 = 0.f, s1 = 0.f;
    for (int k = lane; k < HID; k += 32) {
        float hv = __half2float(xp[k]);
        s0 = fmaf(hv, Wd[k], s0);
        s1 = fmaf(hv, Wd[HID + k], s1);
    }
#pragma unroll
    for (int o = 16; o > 0; o >>= 1) {
        s0 += __shfl_xor_sync(0xffffffffu, s0, o);
        s1 += __shfl_xor_sync(0xffffffffu, s1, o);
    }
    if (lane == 0) {
        Y[(size_t)row * (PH * 2) + t * 2 + 0] = s0 + bd[0];
        Y[(size_t)row * (PH * 2) + t * 2 + 1] = s1 + bd[1];
    }
}

extern "C" void kernel_launch(void* const* d_in, const int* in_sizes, int n_in,
                              void* d_out, int out_size) {
    // metadata order: hist, z, W_ih, W_hh, b_ih, b_hh, W_d, b_d
    const float* z   = (const float*)d_in[1];
    const float* Wih = (const float*)d_in[2];
    const float* Whh = (const float*)d_in[3];
    const float* bih = (const float*)d_in[4];
    const float* bhh = (const float*)d_in[5];
    const float* Wd  = (const float*)d_in[6];
    const float* bd  = (const float*)d_in[7];
    float* Y = (float*)d_out;

    __half *xp, *wp, *wp0;
    cudaGetSymbolAddress((void**)&xp,  g_x);
    cudaGetSymbolAddress((void**)&wp,  g_w);
    cudaGetSymbolAddress((void**)&wp0, g_w0);

    cudaFuncSetAttribute(step_kernel, cudaFuncAttributeMaxDynamicSharedMemorySize, SMEM_DYN);

    prep_w<<<(FOURH * HID + 255) / 256, 256>>>(Wih, Whh, bih, bhh);
    prep_z<<<(BSZ * HID + 255) / 256, 256>>>(z);

    dim3 grid(BSZ / TM, FOURH / TN);   // 16 x 16 = 256 CTAs, 2 per SM
    for (int t = 0; t < PH; ++t) {
        step_kernel<<<grid, NTHR, SMEM_DYN>>>(xp + (size_t)t * SLAB,
                                              t == 0 ? wp0 : wp,
                                              xp + (size_t)(t + 1) * SLAB, t == 0 ? 1 : 0);
    }
    out_all<<<BSZ * PH / 8, 256>>>(Wd, bd, Y);
}

// round 10
// speedup vs baseline: 2.7033x; 1.0484x over previous
#include <cuda_runtime.h>
#include <cuda_fp16.h>
#include <math.h>
#include <stdint.h>

#define HID   512
#define PH    32
#define BSZ   2048
#define FOURH 2048
#define SLAB  (BSZ * HID)

#define TM 128
#define TN 128
#define KC 64
#define NCH (HID / KC)   // 8 k-chunks
#define NTHR 256

// stage layout (bytes): A 128x64 fp16 = 16KB, B 128x64 fp16 = 16KB
#define AH_OFF 0
#define BH_OFF 16384
#define STAGE  32768
#define NSTG   3
#define SMEM_DYN (NSTG * STAGE)   // 96KB -> 2 CTAs/SM

// ---------------- static device scratch ----------------
__device__ __half g_x[(PH + 1) * (size_t)SLAB];   // x_t (fp16), t=0..PH
__device__ __half g_w [FOURH * HID];   // fp16(W_ih + W_hh), permuted
__device__ __half g_w0[FOURH * HID];   // fp16(W_ih), permuted (step 0)
__device__ float g_bp[FOURH];
__device__ float g_c[(size_t)BSZ * HID];

// ---------------- helpers ----------------
__device__ __forceinline__ uint32_t smem_u32(const void* p) {
    uint32_t a;
    asm("{ .reg .u64 t; cvta.to.shared.u64 t, %1; cvt.u32.u64 %0, t; }" : "=r"(a) : "l"(p));
    return a;
}
// 128B rows, 8 x 16B quads, XOR-swizzled: conflict-free for cp.async stores and ldmatrix
__device__ __forceinline__ uint32_t smoff64(int row, int q) {
    return (uint32_t)((row << 7) + (((q) ^ (row & 7)) << 4));
}
__device__ __forceinline__ void cp16(uint32_t dst, const void* src) {
    asm volatile("cp.async.cg.shared.global [%0], [%1], 16;" :: "r"(dst), "l"(src));
}
__device__ __forceinline__ void cp_commit() { asm volatile("cp.async.commit_group;"); }
template <int N>
__device__ __forceinline__ void cp_wait() {
    asm volatile("cp.async.wait_group %0;" :: "n"(N) : "memory");
}
__device__ __forceinline__ void ldsm4(uint32_t* r, uint32_t addr) {
    asm volatile("ldmatrix.sync.aligned.m8n8.x4.shared.b16 {%0,%1,%2,%3}, [%4];"
        : "=r"(r[0]), "=r"(r[1]), "=r"(r[2]), "=r"(r[3]) : "r"(addr));
}
__device__ __forceinline__ void mma16816(float* c, const uint32_t* a,
                                         uint32_t b0, uint32_t b1) {
    asm volatile(
        "mma.sync.aligned.m16n8k16.row.col.f32.f16.f16.f32 "
        "{%0,%1,%2,%3}, {%4,%5,%6,%7}, {%8,%9}, {%0,%1,%2,%3};"
        : "+f"(c[0]), "+f"(c[1]), "+f"(c[2]), "+f"(c[3])
        : "r"(a[0]), "r"(a[1]), "r"(a[2]), "r"(a[3]), "r"(b0), "r"(b1));
}

// ---------------- prep ----------------
// W row r=q*512+hu -> rp = (hu/32)*128 + q*32 + (hu%32): N-tile nb holds 32 units x 4 gates
__global__ void prep_w(const float* __restrict__ Wih, const float* __restrict__ Whh,
                       const float* __restrict__ bih, const float* __restrict__ bhh) {
    int idx = blockIdx.x * blockDim.x + threadIdx.x;
    if (idx >= FOURH * HID) return;
    int r = idx / HID, k = idx - r * HID;
    int q = r >> 9, hu = r & 511;
    int rp = ((hu >> 5) << 7) + (q << 5) + (hu & 31);
    size_t o = (size_t)rp * HID + k;
    g_w0[o] = __float2half_rn(Wih[idx]);
    g_w [o] = __float2half_rn(Wih[idx] + Whh[idx]);
    if (k == 0) g_bp[rp] = bih[r] + bhh[r];
}
__global__ void prep_z(const float* __restrict__ z) {
    int i = blockIdx.x * blockDim.x + threadIdx.x;
    if (i >= BSZ * HID) return;
    g_x[i] = __float2half_rn(z[i]);
}

// ---------------- per-step: gates = X @ W^T (fp16 mma.sync) + fused LSTM epilogue ----
// 8 warps: wm = warp>>2 (M 2x64), wn = warp&3. Warp wn owns n8-blocks {wn, wn+4, wn+8,
// wn+12} = gates i,f,g,o of hidden units [8wn, 8wn+8): epilogue fully register-local.
__global__ __launch_bounds__(NTHR, 2)
void step_kernel(const __half* __restrict__ x, const __half* __restrict__ w,
                 __half* __restrict__ x_o, int t0) {
    extern __shared__ char dyn[];
    __shared__ float bias_sm[TN];
    const int tid = threadIdx.x;
    const int lane = tid & 31, warp = tid >> 5;
    const int wm = warp >> 2, wn = warp & 3;
    const int mb = blockIdx.x, nb = blockIdx.y;

    if (tid < TN) bias_sm[tid] = g_bp[nb * TN + tid];

    // ---- cp.async plan: rows 0..31 (+32*i), quads 0..7; 4 A + 4 B 16B-copies/thread ----
    const int lrow = tid >> 3, lq = tid & 7;
    const __half* a_src = x + (size_t)(mb * TM + lrow) * HID + lq * 8;
    const __half* b_src = w + (size_t)(nb * TN + lrow) * HID + lq * 8;
    const uint32_t a_dst0 = AH_OFF + smoff64(lrow, lq);  // +4096 per 32 rows
    const uint32_t b_dst0 = BH_OFF + smoff64(lrow, lq);

    float acc[4][4][4];   // [mi][gate][frag]
#pragma unroll
    for (int mi = 0; mi < 4; ++mi)
#pragma unroll
        for (int g = 0; g < 4; ++g)
#pragma unroll
            for (int r = 0; r < 4; ++r) acc[mi][g][r] = 0.f;

    // precomputed swizzled ldsm base offsets (stage-relative)
    const int a_row = wm * 64 + (lane & 7) + ((lane >> 3) & 1) * 8;
    const int b_row = 8 * (4 * (lane >> 3) + wn) + (lane & 7);   // n8 block = g*4 + wn
    uint32_t a_base[4], b_base[4][2];
#pragma unroll
    for (int s = 0; s < 4; ++s) {
        a_base[s] = AH_OFF + smoff64(a_row, 2 * s + (lane >> 4));
        b_base[s][0] = BH_OFF + smoff64(b_row, 2 * s);
        b_base[s][1] = BH_OFF + smoff64(b_row, 2 * s + 1);
    }

#pragma unroll
    for (int p = 0; p < 2; ++p) {
        uint32_t sb = smem_u32(dyn + p * STAGE);
        int k0 = p * KC;
#pragma unroll
        for (int i = 0; i < 4; ++i) {
            cp16(sb + a_dst0 + 4096 * i, a_src + (size_t)(32 * i) * HID + k0);
            cp16(sb + b_dst0 + 4096 * i, b_src + (size_t)(32 * i) * HID + k0);
        }
        cp_commit();
    }

#pragma unroll
    for (int c = 0; c < NCH; ++c) {
        if (c + 2 < NCH) cp_wait<1>(); else cp_wait<0>();
        __syncthreads();                 // chunk c resident; stage (c-1)%3 drained
        if (c + 2 < NCH) {
            uint32_t sb = smem_u32(dyn + ((c + 2) % 3) * STAGE);
            int k0 = (c + 2) * KC;
#pragma unroll
            for (int i = 0; i < 4; ++i) {
                cp16(sb + a_dst0 + 4096 * i, a_src + (size_t)(32 * i) * HID + k0);
                cp16(sb + b_dst0 + 4096 * i, b_src + (size_t)(32 * i) * HID + k0);
            }
            cp_commit();
        }
        uint32_t st = smem_u32(dyn + (c % 3) * STAGE);
#pragma unroll
        for (int s = 0; s < 4; ++s) {
            uint32_t r0[4], r1[4];           // B frags: r0 = k0-7, r1 = k8-15, per gate
            ldsm4(r0, st + b_base[s][0]);
            ldsm4(r1, st + b_base[s][1]);
#pragma unroll
            for (int mi = 0; mi < 4; ++mi) {
                uint32_t ah[4];
                ldsm4(ah, st + a_base[s] + 2048 * mi);
#pragma unroll
                for (int g = 0; g < 4; ++g)
                    mma16816(acc[mi][g], ah, r0[g], r1[g]);
            }
        }
    }

    // ---- fused LSTM epilogue, register-local, vectorized stores ----
    const int gq = lane >> 2, sq = lane & 3;
    const int hu = nb * 32 + 8 * wn + 2 * sq;
#pragma unroll
    for (int mi = 0; mi < 4; ++mi) {
#pragma unroll
        for (int rw = 0; rw < 2; ++rw) {
            int row = mb * TM + wm * 64 + mi * 16 + gq + rw * 8;
            size_t off = (size_t)row * HID + hu;
            float2 cold = t0 ? make_float2(0.f, 0.f) : *(const float2*)(g_c + off);
            float hn[2], cn[2];
#pragma unroll
            for (int e = 0; e < 2; ++e) {
                int r = 2 * rw + e, u = 8 * wn + 2 * sq + e;
                float gi = acc[mi][0][r] + bias_sm[u];
                float gf = acc[mi][1][r] + bias_sm[32 + u];
                float gg = acc[mi][2][r] + bias_sm[64 + u];
                float go = acc[mi][3][r] + bias_sm[96 + u];
                float co = e ? cold.y : cold.x;
                float si = 1.f / (1.f + __expf(-gi));
                float sf = 1.f / (1.f + __expf(-gf));
                float so = 1.f / (1.f + __expf(-go));
                float tg = 2.f / (1.f + __expf(-2.f * gg)) - 1.f;
                cn[e] = fmaf(sf, co, si * tg);
                float tc = 2.f / (1.f + __expf(-2.f * cn[e])) - 1.f;
                hn[e] = so * tc;
            }
            *(float2*)(g_c + off) = make_float2(cn[0], cn[1]);
            __half2 h2;
            h2.x = __float2half_rn(hn[0]); h2.y = __float2half_rn(hn[1]);
            *(__half2*)(x_o + off) = h2;
        }
    }
}

// ---------------- final projection: all 32 steps in one kernel ----------------
__global__ void out_all(const float* __restrict__ Wd, const float* __restrict__ bd,
                        float* __restrict__ Y) {
    int wg = blockIdx.x * 8 + (threadIdx.x >> 5);
    int lane = threadIdx.x & 31;
    int t = wg & (PH - 1), row = wg >> 5;
    const __half* xp = g_x + (size_t)(t + 1) * SLAB + (size_t)row * HID;
    float s0 = 0.f, s1 = 0.f;
    for (int k = lane; k < HID; k += 32) {
        float hv = __half2float(xp[k]);
        s0 = fmaf(hv, Wd[k], s0);
        s1 = fmaf(hv, Wd[HID + k], s1);
    }
#pragma unroll
    for (int o = 16; o > 0; o >>= 1) {
        s0 += __shfl_xor_sync(0xffffffffu, s0, o);
        s1 += __shfl_xor_sync(0xffffffffu, s1, o);
    }
    if (lane == 0) {
        Y[(size_t)row * (PH * 2) + t * 2 + 0] = s0 + bd[0];
        Y[(size_t)row * (PH * 2) + t * 2 + 1] = s1 + bd[1];
    }
}

extern "C" void kernel_launch(void* const* d_in, const int* in_sizes, int n_in,
                              void* d_out, int out_size) {
    // metadata order: hist, z, W_ih, W_hh, b_ih, b_hh, W_d, b_d
    const float* z   = (const float*)d_in[1];
    const float* Wih = (const float*)d_in[2];
    const float* Whh = (const float*)d_in[3];
    const float* bih = (const float*)d_in[4];
    const float* bhh = (const float*)d_in[5];
    const float* Wd  = (const float*)d_in[6];
    const float* bd  = (const float*)d_in[7];
    float* Y = (float*)d_out;

    __half *xp, *wp, *wp0;
    cudaGetSymbolAddress((void**)&xp,  g_x);
    cudaGetSymbolAddress((void**)&wp,  g_w);
    cudaGetSymbolAddress((void**)&wp0, g_w0);

    cudaFuncSetAttribute(step_kernel, cudaFuncAttributeMaxDynamicSharedMemorySize, SMEM_DYN);

    prep_w<<<(FOURH * HID + 255) / 256, 256>>>(Wih, Whh, bih, bhh);
    prep_z<<<(BSZ * HID + 255) / 256, 256>>>(z);

    dim3 grid(BSZ / TM, FOURH / TN);   // 16 x 16 = 256 CTAs, 2 per SM
    for (int t = 0; t < PH; ++t) {
        step_kernel<<<grid, NTHR, SMEM_DYN>>>(xp + (size_t)t * SLAB,
                                              t == 0 ? wp0 : wp,
                                              xp + (size_t)(t + 1) * SLAB, t == 0 ? 1 : 0);
    }
    out_all<<<BSZ * PH / 8, 256>>>(Wd, bd, Y);
}